// round 14
// baseline (speedup 1.0000x reference)
#include <cuda_runtime.h>
#include <cuda_bf16.h>
#include <mma.h>
#include <float.h>
#include <stdint.h>

using namespace nvcuda;

#define N_NODES 50000
#define N_PAD   50048
#define N_EDGES 640000
#define D       128
#define OUTF    128
#define TM      128
#define LDS_K   48
#define NBLK    49

// ---------------- device scratch ----------------
__device__ __align__(16) float g_h[N_PAD * D];
__device__ int   g_deg[N_NODES];
__device__ int   g_start[N_NODES + 1];
__device__ int   g_cursor[N_NODES];
__device__ int   g_part[NBLK];
__device__ __align__(16) int2 g_edge[N_EDGES];   // packed (src, weight-bits)

__device__ __forceinline__ int clampN(int v) { return min(max(v, 0), N_NODES - 1); }

// ---------------- CSR build ----------------
__global__ void zero_deg_kernel() {
    int i = blockIdx.x * blockDim.x + threadIdx.x;
    if (i < N_NODES) g_deg[i] = 0;
}

__global__ void hist_kernel(const int* __restrict__ dst) {
    int e = blockIdx.x * blockDim.x + threadIdx.x;
    if (e < N_EDGES) atomicAdd(&g_deg[clampN(dst[e])], 1);
}

__global__ __launch_bounds__(1024) void scan_p1() {
    int t = threadIdx.x, idx = blockIdx.x * 1024 + t;
    int v = (idx < N_NODES) ? g_deg[idx] : 0;
    #pragma unroll
    for (int off = 16; off > 0; off >>= 1) v += __shfl_down_sync(0xFFFFFFFFu, v, off);
    __shared__ int sh[32];
    if ((t & 31) == 0) sh[t >> 5] = v;
    __syncthreads();
    if (t < 32) {
        int x = sh[t];
        #pragma unroll
        for (int off = 16; off > 0; off >>= 1) x += __shfl_down_sync(0xFFFFFFFFu, x, off);
        if (t == 0) g_part[blockIdx.x] = x;
    }
}

// scan p3: warp-shuffle block scan (3 barriers), block offset from g_part
__global__ __launch_bounds__(1024) void scan_p3() {
    __shared__ int swarp[32];
    __shared__ int s_boff;
    const int b = blockIdx.x, t = threadIdx.x, idx = b * 1024 + t;
    const int lane = t & 31, wrp = t >> 5;

    if (t < 32) {                                   // block offset = sum of partials < b
        int acc = 0;
        for (int j = t; j < b; j += 32) acc += g_part[j];
        #pragma unroll
        for (int off = 16; off > 0; off >>= 1) acc += __shfl_down_sync(0xFFFFFFFFu, acc, off);
        if (t == 0) s_boff = acc;
    }

    int v = (idx < N_NODES) ? g_deg[idx] : 0;
    int incl = v;                                   // warp inclusive scan
    #pragma unroll
    for (int off = 1; off < 32; off <<= 1) {
        int x = __shfl_up_sync(0xFFFFFFFFu, incl, off);
        if (lane >= off) incl += x;
    }
    if (lane == 31) swarp[wrp] = incl;
    __syncthreads();
    if (t < 32) {                                   // scan the 32 warp totals
        int x = swarp[t];
        int ws = x;
        #pragma unroll
        for (int off = 1; off < 32; off <<= 1) {
            int y = __shfl_up_sync(0xFFFFFFFFu, ws, off);
            if (t >= off) ws += y;
        }
        swarp[t] = ws - x;                          // exclusive warp offset
    }
    __syncthreads();
    int excl = s_boff + swarp[wrp] + incl - v;
    if (idx < N_NODES) { g_start[idx] = excl; g_cursor[idx] = excl; }
    if (idx == N_NODES - 1) g_start[N_NODES] = excl + v;
}

__global__ void scatter_kernel(const int* __restrict__ src, const int* __restrict__ dst,
                               const float* __restrict__ weight) {
    int e = blockIdx.x * blockDim.x + threadIdx.x;
    if (e >= N_EDGES) return;
    int d = clampN(dst[e]);
    int pos = atomicAdd(&g_cursor[d], 1);
    g_edge[pos] = make_int2(clampN(src[e]), __float_as_int(weight[e]));
}

// ---------------- bf16 split helper ----------------
__device__ __forceinline__ void split_bf16(float x, __nv_bfloat16& h, __nv_bfloat16& l) {
    h = __float2bfloat16_rn(x);
    l = __float2bfloat16_rn(x - __bfloat162float(h));
}

// ---------------- standalone wmma GEMM (gemm1 / gemm2a), K=128 ----------------
static constexpr int SM_REG   = 128 * LDS_K;
static constexpr int SM_F_OFF = 4 * SM_REG * 2;
static constexpr int SMEM_SZ  = SM_F_OFF + 16 * 128 * 4;

template<int WSTR, bool TO_GH>
__global__ __launch_bounds__(256) void gemm_wmma_kernel(const float* __restrict__ A0,
                                                        const float* __restrict__ W,
                                                        const float* __restrict__ bias,
                                                        float* __restrict__ outp) {
    extern __shared__ char smem[];
    __nv_bfloat16* sAhi = (__nv_bfloat16*)smem;
    __nv_bfloat16* sAlo = sAhi + SM_REG;
    __nv_bfloat16* sBhi = sAlo + SM_REG;
    __nv_bfloat16* sBlo = sBhi + SM_REG;
    float*         sF   = (float*)(smem + SM_F_OFF);

    const int tid  = threadIdx.x;
    const int lane = tid & 31;
    const int wid  = tid >> 5;
    const int wm   = wid >> 1;
    const int wn   = wid & 1;
    const int row0 = blockIdx.x * TM;

    float* dstp = TO_GH ? g_h : outp;                 // device symbol ref (shadow-ptr trap!)

    for (int i = tid; i < 16 * 128; i += 256) sF[i] = bias[i & 127];
    __syncthreads();

    wmma::fragment<wmma::accumulator, 16, 16, 16, float> acc[2][4];
    #pragma unroll
    for (int mt = 0; mt < 2; mt++)
        #pragma unroll
        for (int nt = 0; nt < 4; nt++)
            wmma::load_matrix_sync(acc[mt][nt], sF + wn * 64 + nt * 16, 128, wmma::mem_row_major);
    __syncthreads();

    for (int c = 0; c < 4; c++) {
        const int k0 = c * 32;
        if (c > 0) __syncthreads();
        #pragma unroll
        for (int t = 0; t < 4; t++) {
            int g = tid + t * 256;
            int row = g >> 3, kc = (g & 7) * 4;
            int grow = row0 + row;
            float4 v = (grow < N_NODES) ? *(const float4*)&A0[grow * D + k0 + kc]
                                        : make_float4(0.f, 0.f, 0.f, 0.f);
            __nv_bfloat16 h0, h1, h2, h3, l0, l1, l2, l3;
            split_bf16(v.x, h0, l0); split_bf16(v.y, h1, l1);
            split_bf16(v.z, h2, l2); split_bf16(v.w, h3, l3);
            int o = row * LDS_K + kc;
            *(__nv_bfloat162*)&sAhi[o]     = __nv_bfloat162(h0, h1);
            *(__nv_bfloat162*)&sAhi[o + 2] = __nv_bfloat162(h2, h3);
            *(__nv_bfloat162*)&sAlo[o]     = __nv_bfloat162(l0, l1);
            *(__nv_bfloat162*)&sAlo[o + 2] = __nv_bfloat162(l2, l3);
        }
        #pragma unroll
        for (int t = 0; t < 4; t++) {
            int g = tid + t * 256;
            int row = g >> 3, kc = (g & 7) * 4;
            float4 v = *(const float4*)&W[row * WSTR + k0 + kc];
            __nv_bfloat16 h0, h1, h2, h3, l0, l1, l2, l3;
            split_bf16(v.x, h0, l0); split_bf16(v.y, h1, l1);
            split_bf16(v.z, h2, l2); split_bf16(v.w, h3, l3);
            int o = row * LDS_K + kc;
            *(__nv_bfloat162*)&sBhi[o]     = __nv_bfloat162(h0, h1);
            *(__nv_bfloat162*)&sBhi[o + 2] = __nv_bfloat162(h2, h3);
            *(__nv_bfloat162*)&sBlo[o]     = __nv_bfloat162(l0, l1);
            *(__nv_bfloat162*)&sBlo[o + 2] = __nv_bfloat162(l2, l3);
        }
        __syncthreads();

        #pragma unroll
        for (int ks = 0; ks < 2; ks++) {
            const int k16 = ks * 16;
            wmma::fragment<wmma::matrix_a, 16, 16, 16, __nv_bfloat16, wmma::row_major> ahi[2], alo[2];
            #pragma unroll
            for (int mt = 0; mt < 2; mt++) {
                int r = wm * 32 + mt * 16;
                wmma::load_matrix_sync(ahi[mt], &sAhi[r * LDS_K + k16], LDS_K);
                wmma::load_matrix_sync(alo[mt], &sAlo[r * LDS_K + k16], LDS_K);
            }
            #pragma unroll
            for (int nt = 0; nt < 4; nt++) {
                int n = wn * 64 + nt * 16;
                wmma::fragment<wmma::matrix_b, 16, 16, 16, __nv_bfloat16, wmma::col_major> bhi, blo;
                wmma::load_matrix_sync(bhi, &sBhi[n * LDS_K + k16], LDS_K);
                wmma::load_matrix_sync(blo, &sBlo[n * LDS_K + k16], LDS_K);
                #pragma unroll
                for (int mt = 0; mt < 2; mt++) {
                    wmma::mma_sync(acc[mt][nt], ahi[mt], bhi, acc[mt][nt]);
                    wmma::mma_sync(acc[mt][nt], alo[mt], bhi, acc[mt][nt]);
                    wmma::mma_sync(acc[mt][nt], ahi[mt], blo, acc[mt][nt]);
                }
            }
        }
    }

    __syncthreads();
    #pragma unroll
    for (int mt = 0; mt < 2; mt++) {
        int r0 = row0 + wm * 32 + mt * 16;
        #pragma unroll
        for (int nt = 0; nt < 4; nt++) {
            int c0 = wn * 64 + nt * 16;
            if (TO_GH || r0 + 16 <= N_NODES) {
                wmma::store_matrix_sync(&dstp[r0 * OUTF + c0], acc[mt][nt], OUTF, wmma::mem_row_major);
            } else {
                float* st = sF + wid * 256;
                wmma::store_matrix_sync(st, acc[mt][nt], 16, wmma::mem_row_major);
                __syncwarp();
                for (int i = lane; i < 256; i += 32) {
                    int rr = r0 + (i >> 4);
                    if (rr < N_NODES) dstp[rr * OUTF + c0 + (i & 15)] = st[i];
                }
                __syncwarp();
            }
        }
    }
}

// ---------------- FUSED reduce + gemm2b ----------------
// Phase 0: stage B = W_neigh[:,128:256] (128x128) as bf16 hi/lo (stride 136)
// Phase 1: each warp reduces 16 nodes -> bf16 hi/lo planes in smem (stride 136)
// Phase 2: wmma 3-pass, acc initialized from out partial (gemm2a), K=128 in one sweep
#define FS   136                                   // smem row stride (elems)
static constexpr int FN_HI = 0;                    // bf16 plane: 128*136*2 = 34816 B
static constexpr int FN_LO = 34816;
static constexpr int FB_HI = 69632;
static constexpr int FB_LO = 104448;
static constexpr int FF    = 139264;               // fp32 staging 16*128*4 = 8192
static constexpr int FSMEM = 147456;

__global__ __launch_bounds__(256) void fused_reduce_gemm_kernel(const float* __restrict__ W,
                                                                float* __restrict__ outp) {
    extern __shared__ char smem[];
    __nv_bfloat16* sNhi = (__nv_bfloat16*)(smem + FN_HI);
    __nv_bfloat16* sNlo = (__nv_bfloat16*)(smem + FN_LO);
    __nv_bfloat16* sBhi = (__nv_bfloat16*)(smem + FB_HI);
    __nv_bfloat16* sBlo = (__nv_bfloat16*)(smem + FB_LO);
    float*         sF   = (float*)(smem + FF);

    const int tid  = threadIdx.x;
    const int lane = tid & 31;
    const int wid  = tid >> 5;
    const int wm   = wid >> 1;
    const int wn   = wid & 1;
    const int row0 = blockIdx.x * TM;

    // -------- phase 0: stage B (W rows n=0..127, cols k=0..127; W stride 256)
    #pragma unroll
    for (int t = 0; t < 16; t++) {
        int g = tid + t * 256;                      // 4096 granules of 4 floats
        int row = g >> 5, kc = (g & 31) * 4;
        float4 v = *(const float4*)&W[row * 256 + kc];
        __nv_bfloat16 h0, h1, h2, h3, l0, l1, l2, l3;
        split_bf16(v.x, h0, l0); split_bf16(v.y, h1, l1);
        split_bf16(v.z, h2, l2); split_bf16(v.w, h3, l3);
        int o = row * FS + kc;
        *(__nv_bfloat162*)&sBhi[o]     = __nv_bfloat162(h0, h1);
        *(__nv_bfloat162*)&sBhi[o + 2] = __nv_bfloat162(h2, h3);
        *(__nv_bfloat162*)&sBlo[o]     = __nv_bfloat162(l0, l1);
        *(__nv_bfloat162*)&sBlo[o + 2] = __nv_bfloat162(l2, l3);
    }

    // -------- phase 1: warp-per-node reduce, 16 nodes per warp, direct to bf16 planes
    const int col = lane * 4;
    for (int j = 0; j < 16; j++) {
        const int lr   = wid * 16 + j;              // local row 0..127
        const int node = row0 + lr;
        float4 acc = make_float4(-FLT_MAX, -FLT_MAX, -FLT_MAX, -FLT_MAX);
        int beg = 0, end = 0;
        if (node < N_NODES) { beg = g_start[node]; end = g_start[node + 1]; }
        int i = beg;
        for (; i + 4 <= end; i += 4) {
            int2 e0 = g_edge[i],   e1 = g_edge[i+1], e2 = g_edge[i+2], e3 = g_edge[i+3];
            float w0 = __int_as_float(e0.y), w1 = __int_as_float(e1.y);
            float w2 = __int_as_float(e2.y), w3 = __int_as_float(e3.y);
            float4 v0 = *(const float4*)&g_h[e0.x*D + col];
            float4 v1 = *(const float4*)&g_h[e1.x*D + col];
            float4 v2 = *(const float4*)&g_h[e2.x*D + col];
            float4 v3 = *(const float4*)&g_h[e3.x*D + col];
            acc.x = fmaxf(acc.x, v0.x*w0); acc.y = fmaxf(acc.y, v0.y*w0);
            acc.z = fmaxf(acc.z, v0.z*w0); acc.w = fmaxf(acc.w, v0.w*w0);
            acc.x = fmaxf(acc.x, v1.x*w1); acc.y = fmaxf(acc.y, v1.y*w1);
            acc.z = fmaxf(acc.z, v1.z*w1); acc.w = fmaxf(acc.w, v1.w*w1);
            acc.x = fmaxf(acc.x, v2.x*w2); acc.y = fmaxf(acc.y, v2.y*w2);
            acc.z = fmaxf(acc.z, v2.z*w2); acc.w = fmaxf(acc.w, v2.w*w2);
            acc.x = fmaxf(acc.x, v3.x*w3); acc.y = fmaxf(acc.y, v3.y*w3);
            acc.z = fmaxf(acc.z, v3.z*w3); acc.w = fmaxf(acc.w, v3.w*w3);
        }
        for (; i < end; i++) {
            int2 e = g_edge[i];
            float w = __int_as_float(e.y);
            float4 v = *(const float4*)&g_h[e.x*D + col];
            acc.x = fmaxf(acc.x, v.x*w); acc.y = fmaxf(acc.y, v.y*w);
            acc.z = fmaxf(acc.z, v.z*w); acc.w = fmaxf(acc.w, v.w*w);
        }
        if (beg == end) acc = make_float4(0.f, 0.f, 0.f, 0.f);
        __nv_bfloat16 h0, h1, h2, h3, l0, l1, l2, l3;
        split_bf16(acc.x, h0, l0); split_bf16(acc.y, h1, l1);
        split_bf16(acc.z, h2, l2); split_bf16(acc.w, h3, l3);
        int o = lr * FS + col;
        *(__nv_bfloat162*)&sNhi[o]     = __nv_bfloat162(h0, h1);
        *(__nv_bfloat162*)&sNhi[o + 2] = __nv_bfloat162(h2, h3);
        *(__nv_bfloat162*)&sNlo[o]     = __nv_bfloat162(l0, l1);
        *(__nv_bfloat162*)&sNlo[o + 2] = __nv_bfloat162(l2, l3);
    }
    __syncthreads();

    // -------- phase 2: acc init from gemm2a partial, then K=128 wmma sweep
    wmma::fragment<wmma::accumulator, 16, 16, 16, float> acc[2][4];
    #pragma unroll
    for (int mt = 0; mt < 2; mt++) {
        int r0 = row0 + wm * 32 + mt * 16;
        #pragma unroll
        for (int nt = 0; nt < 4; nt++) {
            int c0 = wn * 64 + nt * 16;
            if (r0 + 16 <= N_NODES) {
                wmma::load_matrix_sync(acc[mt][nt], &outp[r0 * OUTF + c0], OUTF, wmma::mem_row_major);
            } else {
                float* st = sF + wid * 256;
                for (int i = lane; i < 256; i += 32) {
                    int rr = min(r0 + (i >> 4), N_NODES - 1);
                    st[i] = outp[rr * OUTF + c0 + (i & 15)];
                }
                __syncwarp();
                wmma::load_matrix_sync(acc[mt][nt], st, 16, wmma::mem_row_major);
                __syncwarp();
            }
        }
    }

    #pragma unroll
    for (int ks = 0; ks < 8; ks++) {
        const int k16 = ks * 16;
        wmma::fragment<wmma::matrix_a, 16, 16, 16, __nv_bfloat16, wmma::row_major> ahi[2], alo[2];
        #pragma unroll
        for (int mt = 0; mt < 2; mt++) {
            int r = wm * 32 + mt * 16;
            wmma::load_matrix_sync(ahi[mt], &sNhi[r * FS + k16], FS);
            wmma::load_matrix_sync(alo[mt], &sNlo[r * FS + k16], FS);
        }
        #pragma unroll
        for (int nt = 0; nt < 4; nt++) {
            int n = wn * 64 + nt * 16;
            wmma::fragment<wmma::matrix_b, 16, 16, 16, __nv_bfloat16, wmma::col_major> bhi, blo;
            wmma::load_matrix_sync(bhi, &sBhi[n * FS + k16], FS);
            wmma::load_matrix_sync(blo, &sBlo[n * FS + k16], FS);
            #pragma unroll
            for (int mt = 0; mt < 2; mt++) {
                wmma::mma_sync(acc[mt][nt], ahi[mt], bhi, acc[mt][nt]);
                wmma::mma_sync(acc[mt][nt], alo[mt], bhi, acc[mt][nt]);
                wmma::mma_sync(acc[mt][nt], ahi[mt], blo, acc[mt][nt]);
            }
        }
    }

    __syncthreads();
    #pragma unroll
    for (int mt = 0; mt < 2; mt++) {
        int r0 = row0 + wm * 32 + mt * 16;
        #pragma unroll
        for (int nt = 0; nt < 4; nt++) {
            int c0 = wn * 64 + nt * 16;
            if (r0 + 16 <= N_NODES) {
                wmma::store_matrix_sync(&outp[r0 * OUTF + c0], acc[mt][nt], OUTF, wmma::mem_row_major);
            } else {
                float* st = sF + wid * 256;
                wmma::store_matrix_sync(st, acc[mt][nt], 16, wmma::mem_row_major);
                __syncwarp();
                for (int i = lane; i < 256; i += 32) {
                    int rr = r0 + (i >> 4);
                    if (rr < N_NODES) outp[rr * OUTF + c0 + (i & 15)] = st[i];
                }
                __syncwarp();
            }
        }
    }
}

// ---------------- launch ----------------
extern "C" void kernel_launch(void* const* d_in, const int* in_sizes, int n_in,
                              void* d_out, int out_size) {
    const float* feat    = (const float*)d_in[0];
    const float* weight  = (const float*)d_in[1];
    const int*   src     = (const int*)d_in[2];
    const int*   dst     = (const int*)d_in[3];
    const float* W_pool  = (const float*)d_in[4];
    const float* b_pool  = (const float*)d_in[5];
    const float* W_neigh = (const float*)d_in[6];
    const float* b_neigh = (const float*)d_in[7];
    float*       out     = (float*)d_out;

    cudaFuncSetAttribute(gemm_wmma_kernel<128, true>,
                         cudaFuncAttributeMaxDynamicSharedMemorySize, SMEM_SZ);
    cudaFuncSetAttribute(gemm_wmma_kernel<256, false>,
                         cudaFuncAttributeMaxDynamicSharedMemorySize, SMEM_SZ);
    cudaFuncSetAttribute(fused_reduce_gemm_kernel,
                         cudaFuncAttributeMaxDynamicSharedMemorySize, FSMEM);

    const int GEMM_GRID = (N_NODES + TM - 1) / TM;   // 391

    cudaStream_t aux;
    cudaStreamCreate(&aux);
    cudaEvent_t evFork, evJ2;
    cudaEventCreateWithFlags(&evFork, cudaEventDisableTiming);
    cudaEventCreateWithFlags(&evJ2,   cudaEventDisableTiming);

    cudaEventRecord(evFork, 0);
    cudaStreamWaitEvent(aux, evFork, 0);

    // main: CSR build chain
    zero_deg_kernel<<<(N_NODES + 255) / 256, 256>>>();
    hist_kernel<<<(N_EDGES + 255) / 256, 256>>>(dst);
    scan_p1<<<NBLK, 1024>>>();
    scan_p3<<<NBLK, 1024>>>();
    scatter_kernel<<<(N_EDGES + 255) / 256, 256>>>(src, dst, weight);

    // aux: gemm1 (-> g_h), then gemm2a (feat half -> out partial)
    gemm_wmma_kernel<128, true><<<GEMM_GRID, 256, SMEM_SZ, aux>>>(feat, W_pool, b_pool, nullptr);
    gemm_wmma_kernel<256, false><<<GEMM_GRID, 256, SMEM_SZ, aux>>>(feat, W_neigh, b_neigh, out);
    cudaEventRecord(evJ2, aux);

    // main: fused reduce+gemm2b needs scatter (main) + gemm1/gemm2a (evJ2)
    cudaStreamWaitEvent(0, evJ2, 0);
    fused_reduce_gemm_kernel<<<GEMM_GRID, 256, FSMEM>>>(W_neigh + D, out);
}

// round 15
// speedup vs baseline: 1.4371x; 1.4371x over previous
#include <cuda_runtime.h>
#include <cuda_bf16.h>
#include <mma.h>
#include <float.h>
#include <stdint.h>

using namespace nvcuda;

#define N_NODES 50000
#define N_PAD   50048
#define N_EDGES 640000
#define D       128
#define OUTF    128
#define TM      128
#define LDS_K   48
#define NBLK    49
#define NTILES  391             // ceil(N_NODES/128)
#define TILES_A 196             // chunk A tiles; nodes [0, 25088)
#define NODES_A (TILES_A * TM)  // 25088

// ---------------- device scratch ----------------
__device__ __align__(16) float g_h[N_PAD * D];
__device__ __align__(16) float g_neigh[N_NODES * D];
__device__ int   g_deg[N_NODES];
__device__ int   g_start[N_NODES + 1];
__device__ int   g_cursor[N_NODES];
__device__ int   g_part[NBLK];
__device__ __align__(16) int2 g_edge[N_EDGES];   // packed (src, weight-bits)

__device__ __forceinline__ int clampN(int v) { return min(max(v, 0), N_NODES - 1); }

// ---------------- CSR build ----------------
__global__ void zero_deg_kernel() {
    int i = blockIdx.x * blockDim.x + threadIdx.x;
    if (i < N_NODES) g_deg[i] = 0;
}

__global__ void hist_kernel(const int* __restrict__ dst) {
    int e = blockIdx.x * blockDim.x + threadIdx.x;
    if (e < N_EDGES) atomicAdd(&g_deg[clampN(dst[e])], 1);
}

__global__ __launch_bounds__(1024) void scan_p1() {
    int t = threadIdx.x, idx = blockIdx.x * 1024 + t;
    int v = (idx < N_NODES) ? g_deg[idx] : 0;
    #pragma unroll
    for (int off = 16; off > 0; off >>= 1) v += __shfl_down_sync(0xFFFFFFFFu, v, off);
    __shared__ int sh[32];
    if ((t & 31) == 0) sh[t >> 5] = v;
    __syncthreads();
    if (t < 32) {
        int x = sh[t];
        #pragma unroll
        for (int off = 16; off > 0; off >>= 1) x += __shfl_down_sync(0xFFFFFFFFu, x, off);
        if (t == 0) g_part[blockIdx.x] = x;
    }
}

// scan p3: warp-shuffle block scan, block offset from g_part
__global__ __launch_bounds__(1024) void scan_p3() {
    __shared__ int swarp[32];
    __shared__ int s_boff;
    const int b = blockIdx.x, t = threadIdx.x, idx = b * 1024 + t;
    const int lane = t & 31, wrp = t >> 5;

    if (t < 32) {
        int acc = 0;
        for (int j = t; j < b; j += 32) acc += g_part[j];
        #pragma unroll
        for (int off = 16; off > 0; off >>= 1) acc += __shfl_down_sync(0xFFFFFFFFu, acc, off);
        if (t == 0) s_boff = acc;
    }

    int v = (idx < N_NODES) ? g_deg[idx] : 0;
    int incl = v;
    #pragma unroll
    for (int off = 1; off < 32; off <<= 1) {
        int x = __shfl_up_sync(0xFFFFFFFFu, incl, off);
        if (lane >= off) incl += x;
    }
    if (lane == 31) swarp[wrp] = incl;
    __syncthreads();
    if (t < 32) {
        int x = swarp[t];
        int ws = x;
        #pragma unroll
        for (int off = 1; off < 32; off <<= 1) {
            int y = __shfl_up_sync(0xFFFFFFFFu, ws, off);
            if (t >= off) ws += y;
        }
        swarp[t] = ws - x;
    }
    __syncthreads();
    int excl = s_boff + swarp[wrp] + incl - v;
    if (idx < N_NODES) { g_start[idx] = excl; g_cursor[idx] = excl; }
    if (idx == N_NODES - 1) g_start[N_NODES] = excl + v;
}

__global__ void scatter_kernel(const int* __restrict__ src, const int* __restrict__ dst,
                               const float* __restrict__ weight) {
    int e = blockIdx.x * blockDim.x + threadIdx.x;
    if (e >= N_EDGES) return;
    int d = clampN(dst[e]);
    int pos = atomicAdd(&g_cursor[d], 1);
    g_edge[pos] = make_int2(clampN(src[e]), __float_as_int(weight[e]));
}

// ---------------- warp-per-node max reduce (node range [node0, node0+nn)) ----------------
__global__ __launch_bounds__(256) void reduce_kernel(int node0, int nn) {
    const int node = node0 + (blockIdx.x << 3) + (threadIdx.x >> 5);
    const int lane = threadIdx.x & 31;
    if (node >= node0 + nn || node >= N_NODES) return;
    const int beg = g_start[node], end = g_start[node + 1];
    const int col = lane * 4;
    float4 acc = make_float4(-FLT_MAX, -FLT_MAX, -FLT_MAX, -FLT_MAX);
    int i = beg;
    for (; i + 4 <= end; i += 4) {
        int2 e0 = g_edge[i],   e1 = g_edge[i+1], e2 = g_edge[i+2], e3 = g_edge[i+3];
        float w0 = __int_as_float(e0.y), w1 = __int_as_float(e1.y);
        float w2 = __int_as_float(e2.y), w3 = __int_as_float(e3.y);
        float4 v0 = *(const float4*)&g_h[e0.x*D + col];
        float4 v1 = *(const float4*)&g_h[e1.x*D + col];
        float4 v2 = *(const float4*)&g_h[e2.x*D + col];
        float4 v3 = *(const float4*)&g_h[e3.x*D + col];
        acc.x = fmaxf(acc.x, v0.x*w0); acc.y = fmaxf(acc.y, v0.y*w0);
        acc.z = fmaxf(acc.z, v0.z*w0); acc.w = fmaxf(acc.w, v0.w*w0);
        acc.x = fmaxf(acc.x, v1.x*w1); acc.y = fmaxf(acc.y, v1.y*w1);
        acc.z = fmaxf(acc.z, v1.z*w1); acc.w = fmaxf(acc.w, v1.w*w1);
        acc.x = fmaxf(acc.x, v2.x*w2); acc.y = fmaxf(acc.y, v2.y*w2);
        acc.z = fmaxf(acc.z, v2.z*w2); acc.w = fmaxf(acc.w, v2.w*w2);
        acc.x = fmaxf(acc.x, v3.x*w3); acc.y = fmaxf(acc.y, v3.y*w3);
        acc.z = fmaxf(acc.z, v3.z*w3); acc.w = fmaxf(acc.w, v3.w*w3);
    }
    for (; i < end; i++) {
        int2 e = g_edge[i];
        float w = __int_as_float(e.y);
        float4 v = *(const float4*)&g_h[e.x*D + col];
        acc.x = fmaxf(acc.x, v.x*w); acc.y = fmaxf(acc.y, v.y*w);
        acc.z = fmaxf(acc.z, v.z*w); acc.w = fmaxf(acc.w, v.w*w);
    }
    float4 outv = (beg == end) ? make_float4(0.f, 0.f, 0.f, 0.f) : acc;
    *(float4*)&g_neigh[node*D + col] = outv;
}

// ---------------- bf16 split helper ----------------
__device__ __forceinline__ void split_bf16(float x, __nv_bfloat16& h, __nv_bfloat16& l) {
    h = __float2bfloat16_rn(x);
    l = __float2bfloat16_rn(x - __bfloat162float(h));
}

// ---------------- wmma bf16 3-pass GEMM, K=128 ----------------
static constexpr int SM_REG   = 128 * LDS_K;
static constexpr int SM_F_OFF = 4 * SM_REG * 2;
static constexpr int SMEM_SZ  = SM_F_OFF + 16 * 128 * 4;

template<bool A_NEIGH, int WSTR, bool TO_GH, bool ACCUM>
__global__ __launch_bounds__(256) void gemm_wmma_kernel(const float* __restrict__ A0,
                                                        const float* __restrict__ W,
                                                        const float* __restrict__ bias,
                                                        float* __restrict__ outp,
                                                        int tile0) {
    extern __shared__ char smem[];
    __nv_bfloat16* sAhi = (__nv_bfloat16*)smem;
    __nv_bfloat16* sAlo = sAhi + SM_REG;
    __nv_bfloat16* sBhi = sAlo + SM_REG;
    __nv_bfloat16* sBlo = sBhi + SM_REG;
    float*         sF   = (float*)(smem + SM_F_OFF);

    const int tid  = threadIdx.x;
    const int lane = tid & 31;
    const int wid  = tid >> 5;
    const int wm   = wid >> 1;
    const int wn   = wid & 1;
    const int row0 = (blockIdx.x + tile0) * TM;

    float* dstp = TO_GH ? g_h : outp;                 // device symbol ref (shadow-ptr trap!)
    const float* Asrc = A_NEIGH ? (const float*)g_neigh : A0;

    wmma::fragment<wmma::accumulator, 16, 16, 16, float> acc[2][4];
    if (!ACCUM) {
        for (int i = tid; i < 16 * 128; i += 256) sF[i] = bias[i & 127];
        __syncthreads();
        #pragma unroll
        for (int mt = 0; mt < 2; mt++)
            #pragma unroll
            for (int nt = 0; nt < 4; nt++)
                wmma::load_matrix_sync(acc[mt][nt], sF + wn * 64 + nt * 16, 128, wmma::mem_row_major);
        __syncthreads();
    } else {
        #pragma unroll
        for (int mt = 0; mt < 2; mt++) {
            int r0 = row0 + wm * 32 + mt * 16;
            #pragma unroll
            for (int nt = 0; nt < 4; nt++) {
                int c0 = wn * 64 + nt * 16;
                if (r0 + 16 <= N_NODES) {
                    wmma::load_matrix_sync(acc[mt][nt], &outp[r0 * OUTF + c0], OUTF, wmma::mem_row_major);
                } else {
                    float* st = sF + wid * 256;
                    for (int i = lane; i < 256; i += 32) {
                        int rr = min(r0 + (i >> 4), N_NODES - 1);
                        st[i] = outp[rr * OUTF + c0 + (i & 15)];
                    }
                    __syncwarp();
                    wmma::load_matrix_sync(acc[mt][nt], st, 16, wmma::mem_row_major);
                    __syncwarp();
                }
            }
        }
        __syncthreads();
    }

    for (int c = 0; c < 4; c++) {
        const int k0 = c * 32;
        if (c > 0) __syncthreads();

        #pragma unroll
        for (int t = 0; t < 4; t++) {
            int g = tid + t * 256;
            int row = g >> 3, kc = (g & 7) * 4;
            int grow = row0 + row;
            float4 v = (grow < N_NODES) ? *(const float4*)&Asrc[grow * D + k0 + kc]
                                        : make_float4(0.f, 0.f, 0.f, 0.f);
            __nv_bfloat16 h0, h1, h2, h3, l0, l1, l2, l3;
            split_bf16(v.x, h0, l0); split_bf16(v.y, h1, l1);
            split_bf16(v.z, h2, l2); split_bf16(v.w, h3, l3);
            int o = row * LDS_K + kc;
            *(__nv_bfloat162*)&sAhi[o]     = __nv_bfloat162(h0, h1);
            *(__nv_bfloat162*)&sAhi[o + 2] = __nv_bfloat162(h2, h3);
            *(__nv_bfloat162*)&sAlo[o]     = __nv_bfloat162(l0, l1);
            *(__nv_bfloat162*)&sAlo[o + 2] = __nv_bfloat162(l2, l3);
        }
        #pragma unroll
        for (int t = 0; t < 4; t++) {
            int g = tid + t * 256;
            int row = g >> 3, kc = (g & 7) * 4;
            float4 v = *(const float4*)&W[row * WSTR + k0 + kc];
            __nv_bfloat16 h0, h1, h2, h3, l0, l1, l2, l3;
            split_bf16(v.x, h0, l0); split_bf16(v.y, h1, l1);
            split_bf16(v.z, h2, l2); split_bf16(v.w, h3, l3);
            int o = row * LDS_K + kc;
            *(__nv_bfloat162*)&sBhi[o]     = __nv_bfloat162(h0, h1);
            *(__nv_bfloat162*)&sBhi[o + 2] = __nv_bfloat162(h2, h3);
            *(__nv_bfloat162*)&sBlo[o]     = __nv_bfloat162(l0, l1);
            *(__nv_bfloat162*)&sBlo[o + 2] = __nv_bfloat162(l2, l3);
        }
        __syncthreads();

        #pragma unroll
        for (int ks = 0; ks < 2; ks++) {
            const int k16 = ks * 16;
            wmma::fragment<wmma::matrix_a, 16, 16, 16, __nv_bfloat16, wmma::row_major> ahi[2], alo[2];
            #pragma unroll
            for (int mt = 0; mt < 2; mt++) {
                int r = wm * 32 + mt * 16;
                wmma::load_matrix_sync(ahi[mt], &sAhi[r * LDS_K + k16], LDS_K);
                wmma::load_matrix_sync(alo[mt], &sAlo[r * LDS_K + k16], LDS_K);
            }
            #pragma unroll
            for (int nt = 0; nt < 4; nt++) {
                int n = wn * 64 + nt * 16;
                wmma::fragment<wmma::matrix_b, 16, 16, 16, __nv_bfloat16, wmma::col_major> bhi, blo;
                wmma::load_matrix_sync(bhi, &sBhi[n * LDS_K + k16], LDS_K);
                wmma::load_matrix_sync(blo, &sBlo[n * LDS_K + k16], LDS_K);
                #pragma unroll
                for (int mt = 0; mt < 2; mt++) {
                    wmma::mma_sync(acc[mt][nt], ahi[mt], bhi, acc[mt][nt]);
                    wmma::mma_sync(acc[mt][nt], alo[mt], bhi, acc[mt][nt]);
                    wmma::mma_sync(acc[mt][nt], ahi[mt], blo, acc[mt][nt]);
                }
            }
        }
    }

    __syncthreads();
    #pragma unroll
    for (int mt = 0; mt < 2; mt++) {
        int r0 = row0 + wm * 32 + mt * 16;
        #pragma unroll
        for (int nt = 0; nt < 4; nt++) {
            int c0 = wn * 64 + nt * 16;
            if (TO_GH || r0 + 16 <= N_NODES) {
                wmma::store_matrix_sync(&dstp[r0 * OUTF + c0], acc[mt][nt], OUTF, wmma::mem_row_major);
            } else {
                float* st = sF + wid * 256;
                wmma::store_matrix_sync(st, acc[mt][nt], 16, wmma::mem_row_major);
                __syncwarp();
                for (int i = lane; i < 256; i += 32) {
                    int rr = r0 + (i >> 4);
                    if (rr < N_NODES) dstp[rr * OUTF + c0 + (i & 15)] = st[i];
                }
                __syncwarp();
            }
        }
    }
}

// ---------------- launch ----------------
extern "C" void kernel_launch(void* const* d_in, const int* in_sizes, int n_in,
                              void* d_out, int out_size) {
    const float* feat    = (const float*)d_in[0];
    const float* weight  = (const float*)d_in[1];
    const int*   src     = (const int*)d_in[2];
    const int*   dst     = (const int*)d_in[3];
    const float* W_pool  = (const float*)d_in[4];
    const float* b_pool  = (const float*)d_in[5];
    const float* W_neigh = (const float*)d_in[6];
    const float* b_neigh = (const float*)d_in[7];
    float*       out     = (float*)d_out;

    cudaFuncSetAttribute(gemm_wmma_kernel<false, 128, true,  false>,
                         cudaFuncAttributeMaxDynamicSharedMemorySize, SMEM_SZ);
    cudaFuncSetAttribute(gemm_wmma_kernel<false, 256, false, false>,
                         cudaFuncAttributeMaxDynamicSharedMemorySize, SMEM_SZ);
    cudaFuncSetAttribute(gemm_wmma_kernel<true,  256, false, true>,
                         cudaFuncAttributeMaxDynamicSharedMemorySize, SMEM_SZ);

    cudaStream_t aux;
    cudaStreamCreate(&aux);
    cudaEvent_t evFork, evJ1, evJ2, evRA, evDone;
    cudaEventCreateWithFlags(&evFork, cudaEventDisableTiming);
    cudaEventCreateWithFlags(&evJ1,   cudaEventDisableTiming);
    cudaEventCreateWithFlags(&evJ2,   cudaEventDisableTiming);
    cudaEventCreateWithFlags(&evRA,   cudaEventDisableTiming);
    cudaEventCreateWithFlags(&evDone, cudaEventDisableTiming);

    cudaEventRecord(evFork, 0);
    cudaStreamWaitEvent(aux, evFork, 0);

    // main: CSR build chain
    zero_deg_kernel<<<(N_NODES + 255) / 256, 256>>>();
    hist_kernel<<<(N_EDGES + 255) / 256, 256>>>(dst);
    scan_p1<<<NBLK, 1024>>>();
    scan_p3<<<NBLK, 1024>>>();
    scatter_kernel<<<(N_EDGES + 255) / 256, 256>>>(src, dst, weight);

    // aux: gemm1 (-> g_h), then gemm2a (feat half -> out partial)
    gemm_wmma_kernel<false, 128, true, false><<<NTILES, 256, SMEM_SZ, aux>>>(feat, W_pool, b_pool, nullptr, 0);
    cudaEventRecord(evJ1, aux);
    gemm_wmma_kernel<false, 256, false, false><<<NTILES, 256, SMEM_SZ, aux>>>(feat, W_neigh, b_neigh, out, 0);
    cudaEventRecord(evJ2, aux);

    // main: reduce chunk A (needs scatter + gemm1)
    cudaStreamWaitEvent(0, evJ1, 0);
    reduce_kernel<<<NODES_A / 8, 256>>>(0, NODES_A);
    cudaEventRecord(evRA, 0);

    // main: reduce chunk B
    reduce_kernel<<<(N_NODES - NODES_A + 7) / 8, 256>>>(NODES_A, N_NODES - NODES_A);

    // aux: gemm2b chunk A overlaps reduce chunk B (gemm2a already sequenced on aux)
    cudaStreamWaitEvent(aux, evRA, 0);
    gemm_wmma_kernel<true, 256, false, true><<<TILES_A, 256, SMEM_SZ, aux>>>(nullptr, W_neigh + D, b_neigh, out, 0);
    cudaEventRecord(evDone, aux);

    // main: gemm2b chunk B (needs reduce B in-order + gemm2a)
    cudaStreamWaitEvent(0, evJ2, 0);
    gemm_wmma_kernel<true, 256, false, true><<<NTILES - TILES_A, 256, SMEM_SZ>>>(nullptr, W_neigh + D, b_neigh, out, TILES_A);

    // join aux back into main before returning
    cudaStreamWaitEvent(0, evDone, 0);
}

// round 16
// speedup vs baseline: 1.4589x; 1.0152x over previous
#include <cuda_runtime.h>
#include <cuda_bf16.h>
#include <mma.h>
#include <float.h>
#include <stdint.h>

using namespace nvcuda;

#define N_NODES 50000
#define N_PAD   50048
#define N_EDGES 640000
#define D       128
#define OUTF    128
#define TM      128
#define LDS_K   48
#define NBLK    49
#define NTILES  391

// ---------------- device scratch ----------------
__device__ __align__(16) float g_h[N_PAD * D];
__device__ __align__(16) __nv_bfloat16 g_nhi[N_PAD * D];   // neigh hi plane
__device__ __align__(16) __nv_bfloat16 g_nlo[N_PAD * D];   // neigh lo plane
__device__ int   g_deg[N_NODES];
__device__ int   g_start[N_NODES + 1];
__device__ int   g_cursor[N_NODES];
__device__ int   g_part[NBLK];
__device__ __align__(16) int2 g_edge[N_EDGES];   // packed (src, weight-bits)

__device__ __forceinline__ int clampN(int v) { return min(max(v, 0), N_NODES - 1); }

__device__ __forceinline__ void split_bf16(float x, __nv_bfloat16& h, __nv_bfloat16& l) {
    h = __float2bfloat16_rn(x);
    l = __float2bfloat16_rn(x - __bfloat162float(h));
}
__device__ __forceinline__ unsigned pack2(__nv_bfloat16 a, __nv_bfloat16 b) {
    __nv_bfloat162 t(a, b);
    return *(unsigned*)&t;
}

// ---------------- CSR build ----------------
__global__ void zero_deg_kernel() {
    int i = blockIdx.x * blockDim.x + threadIdx.x;
    if (i < N_NODES) g_deg[i] = 0;
}

__global__ void hist_kernel(const int* __restrict__ dst) {
    int e = blockIdx.x * blockDim.x + threadIdx.x;
    if (e < N_EDGES) atomicAdd(&g_deg[clampN(dst[e])], 1);
}

__global__ __launch_bounds__(1024) void scan_p1() {
    int t = threadIdx.x, idx = blockIdx.x * 1024 + t;
    int v = (idx < N_NODES) ? g_deg[idx] : 0;
    #pragma unroll
    for (int off = 16; off > 0; off >>= 1) v += __shfl_down_sync(0xFFFFFFFFu, v, off);
    __shared__ int sh[32];
    if ((t & 31) == 0) sh[t >> 5] = v;
    __syncthreads();
    if (t < 32) {
        int x = sh[t];
        #pragma unroll
        for (int off = 16; off > 0; off >>= 1) x += __shfl_down_sync(0xFFFFFFFFu, x, off);
        if (t == 0) g_part[blockIdx.x] = x;
    }
}

// scan p3: warp-shuffle block scan, block offset from g_part
__global__ __launch_bounds__(1024) void scan_p3() {
    __shared__ int swarp[32];
    __shared__ int s_boff;
    const int b = blockIdx.x, t = threadIdx.x, idx = b * 1024 + t;
    const int lane = t & 31, wrp = t >> 5;

    if (t < 32) {
        int acc = 0;
        for (int j = t; j < b; j += 32) acc += g_part[j];
        #pragma unroll
        for (int off = 16; off > 0; off >>= 1) acc += __shfl_down_sync(0xFFFFFFFFu, acc, off);
        if (t == 0) s_boff = acc;
    }

    int v = (idx < N_NODES) ? g_deg[idx] : 0;
    int incl = v;
    #pragma unroll
    for (int off = 1; off < 32; off <<= 1) {
        int x = __shfl_up_sync(0xFFFFFFFFu, incl, off);
        if (lane >= off) incl += x;
    }
    if (lane == 31) swarp[wrp] = incl;
    __syncthreads();
    if (t < 32) {
        int x = swarp[t];
        int ws = x;
        #pragma unroll
        for (int off = 1; off < 32; off <<= 1) {
            int y = __shfl_up_sync(0xFFFFFFFFu, ws, off);
            if (t >= off) ws += y;
        }
        swarp[t] = ws - x;
    }
    __syncthreads();
    int excl = s_boff + swarp[wrp] + incl - v;
    if (idx < N_NODES) { g_start[idx] = excl; g_cursor[idx] = excl; }
    if (idx == N_NODES - 1) g_start[N_NODES] = excl + v;
}

__global__ void scatter_kernel(const int* __restrict__ src, const int* __restrict__ dst,
                               const float* __restrict__ weight) {
    int e = blockIdx.x * blockDim.x + threadIdx.x;
    if (e >= N_EDGES) return;
    int d = clampN(dst[e]);
    int pos = atomicAdd(&g_cursor[d], 1);
    g_edge[pos] = make_int2(clampN(src[e]), __float_as_int(weight[e]));
}

// ---------------- warp-per-node max reduce -> bf16 hi/lo planes ----------------
__global__ __launch_bounds__(256) void reduce_kernel() {
    const int node = (blockIdx.x << 3) + (threadIdx.x >> 5);
    const int lane = threadIdx.x & 31;
    if (node >= N_NODES) return;
    const int beg = g_start[node], end = g_start[node + 1];
    const int col = lane * 4;
    float4 acc = make_float4(-FLT_MAX, -FLT_MAX, -FLT_MAX, -FLT_MAX);
    int i = beg;
    for (; i + 4 <= end; i += 4) {
        int2 e0 = g_edge[i],   e1 = g_edge[i+1], e2 = g_edge[i+2], e3 = g_edge[i+3];
        float w0 = __int_as_float(e0.y), w1 = __int_as_float(e1.y);
        float w2 = __int_as_float(e2.y), w3 = __int_as_float(e3.y);
        float4 v0 = *(const float4*)&g_h[e0.x*D + col];
        float4 v1 = *(const float4*)&g_h[e1.x*D + col];
        float4 v2 = *(const float4*)&g_h[e2.x*D + col];
        float4 v3 = *(const float4*)&g_h[e3.x*D + col];
        acc.x = fmaxf(acc.x, v0.x*w0); acc.y = fmaxf(acc.y, v0.y*w0);
        acc.z = fmaxf(acc.z, v0.z*w0); acc.w = fmaxf(acc.w, v0.w*w0);
        acc.x = fmaxf(acc.x, v1.x*w1); acc.y = fmaxf(acc.y, v1.y*w1);
        acc.z = fmaxf(acc.z, v1.z*w1); acc.w = fmaxf(acc.w, v1.w*w1);
        acc.x = fmaxf(acc.x, v2.x*w2); acc.y = fmaxf(acc.y, v2.y*w2);
        acc.z = fmaxf(acc.z, v2.z*w2); acc.w = fmaxf(acc.w, v2.w*w2);
        acc.x = fmaxf(acc.x, v3.x*w3); acc.y = fmaxf(acc.y, v3.y*w3);
        acc.z = fmaxf(acc.z, v3.z*w3); acc.w = fmaxf(acc.w, v3.w*w3);
    }
    for (; i < end; i++) {
        int2 e = g_edge[i];
        float w = __int_as_float(e.y);
        float4 v = *(const float4*)&g_h[e.x*D + col];
        acc.x = fmaxf(acc.x, v.x*w); acc.y = fmaxf(acc.y, v.y*w);
        acc.z = fmaxf(acc.z, v.z*w); acc.w = fmaxf(acc.w, v.w*w);
    }
    if (beg == end) acc = make_float4(0.f, 0.f, 0.f, 0.f);
    __nv_bfloat16 h0, h1, h2, h3, l0, l1, l2, l3;
    split_bf16(acc.x, h0, l0); split_bf16(acc.y, h1, l1);
    split_bf16(acc.z, h2, l2); split_bf16(acc.w, h3, l3);
    *(uint2*)&g_nhi[node*D + col] = make_uint2(pack2(h0, h1), pack2(h2, h3));
    *(uint2*)&g_nlo[node*D + col] = make_uint2(pack2(l0, l1), pack2(l2, l3));
}

// ---------------- wmma bf16 3-pass GEMM, K=128 ----------------
// A_PLANES: A tile comes pre-split from g_nhi/g_nlo (no converts in stage loop)
static constexpr int SM_REG   = 128 * LDS_K;
static constexpr int SM_F_OFF = 4 * SM_REG * 2;
static constexpr int SMEM_SZ  = SM_F_OFF + 16 * 128 * 4;

template<bool A_PLANES, int WSTR, bool TO_GH, bool ACCUM>
__global__ __launch_bounds__(256) void gemm_wmma_kernel(const float* __restrict__ A0,
                                                        const float* __restrict__ W,
                                                        const float* __restrict__ bias,
                                                        float* __restrict__ outp) {
    extern __shared__ char smem[];
    __nv_bfloat16* sAhi = (__nv_bfloat16*)smem;
    __nv_bfloat16* sAlo = sAhi + SM_REG;
    __nv_bfloat16* sBhi = sAlo + SM_REG;
    __nv_bfloat16* sBlo = sBhi + SM_REG;
    float*         sF   = (float*)(smem + SM_F_OFF);

    const int tid  = threadIdx.x;
    const int lane = tid & 31;
    const int wid  = tid >> 5;
    const int wm   = wid >> 1;
    const int wn   = wid & 1;
    const int row0 = blockIdx.x * TM;

    float* dstp = TO_GH ? g_h : outp;                 // device symbol ref (shadow-ptr trap!)

    wmma::fragment<wmma::accumulator, 16, 16, 16, float> acc[2][4];
    if (!ACCUM) {
        for (int i = tid; i < 16 * 128; i += 256) sF[i] = bias[i & 127];
        __syncthreads();
        #pragma unroll
        for (int mt = 0; mt < 2; mt++)
            #pragma unroll
            for (int nt = 0; nt < 4; nt++)
                wmma::load_matrix_sync(acc[mt][nt], sF + wn * 64 + nt * 16, 128, wmma::mem_row_major);
        __syncthreads();
    } else {
        #pragma unroll
        for (int mt = 0; mt < 2; mt++) {
            int r0 = row0 + wm * 32 + mt * 16;
            #pragma unroll
            for (int nt = 0; nt < 4; nt++) {
                int c0 = wn * 64 + nt * 16;
                if (r0 + 16 <= N_NODES) {
                    wmma::load_matrix_sync(acc[mt][nt], &outp[r0 * OUTF + c0], OUTF, wmma::mem_row_major);
                } else {
                    float* st = sF + wid * 256;
                    for (int i = lane; i < 256; i += 32) {
                        int rr = min(r0 + (i >> 4), N_NODES - 1);
                        st[i] = outp[rr * OUTF + c0 + (i & 15)];
                    }
                    __syncwarp();
                    wmma::load_matrix_sync(acc[mt][nt], st, 16, wmma::mem_row_major);
                    __syncwarp();
                }
            }
        }
        __syncthreads();
    }

    for (int c = 0; c < 4; c++) {
        const int k0 = c * 32;
        if (c > 0) __syncthreads();

        #pragma unroll
        for (int t = 0; t < 4; t++) {                 // A chunk
            int g = tid + t * 256;
            int row = g >> 3, kc = (g & 7) * 4;
            int grow = row0 + row;
            int o = row * LDS_K + kc;
            if (A_PLANES) {
                uint2 vh = (grow < N_NODES) ? *(const uint2*)&g_nhi[grow * D + k0 + kc]
                                            : make_uint2(0, 0);
                uint2 vl = (grow < N_NODES) ? *(const uint2*)&g_nlo[grow * D + k0 + kc]
                                            : make_uint2(0, 0);
                *(uint2*)&sAhi[o] = vh;
                *(uint2*)&sAlo[o] = vl;
            } else {
                float4 v = (grow < N_NODES) ? *(const float4*)&A0[grow * D + k0 + kc]
                                            : make_float4(0.f, 0.f, 0.f, 0.f);
                __nv_bfloat16 h0, h1, h2, h3, l0, l1, l2, l3;
                split_bf16(v.x, h0, l0); split_bf16(v.y, h1, l1);
                split_bf16(v.z, h2, l2); split_bf16(v.w, h3, l3);
                *(uint2*)&sAhi[o] = make_uint2(pack2(h0, h1), pack2(h2, h3));
                *(uint2*)&sAlo[o] = make_uint2(pack2(l0, l1), pack2(l2, l3));
            }
        }
        #pragma unroll
        for (int t = 0; t < 4; t++) {                 // B chunk: W[n][k], stride WSTR
            int g = tid + t * 256;
            int row = g >> 3, kc = (g & 7) * 4;
            float4 v = *(const float4*)&W[row * WSTR + k0 + kc];
            __nv_bfloat16 h0, h1, h2, h3, l0, l1, l2, l3;
            split_bf16(v.x, h0, l0); split_bf16(v.y, h1, l1);
            split_bf16(v.z, h2, l2); split_bf16(v.w, h3, l3);
            int o = row * LDS_K + kc;
            *(uint2*)&sBhi[o] = make_uint2(pack2(h0, h1), pack2(h2, h3));
            *(uint2*)&sBlo[o] = make_uint2(pack2(l0, l1), pack2(l2, l3));
        }
        __syncthreads();

        #pragma unroll
        for (int ks = 0; ks < 2; ks++) {
            const int k16 = ks * 16;
            wmma::fragment<wmma::matrix_a, 16, 16, 16, __nv_bfloat16, wmma::row_major> ahi[2], alo[2];
            #pragma unroll
            for (int mt = 0; mt < 2; mt++) {
                int r = wm * 32 + mt * 16;
                wmma::load_matrix_sync(ahi[mt], &sAhi[r * LDS_K + k16], LDS_K);
                wmma::load_matrix_sync(alo[mt], &sAlo[r * LDS_K + k16], LDS_K);
            }
            #pragma unroll
            for (int nt = 0; nt < 4; nt++) {
                int n = wn * 64 + nt * 16;
                wmma::fragment<wmma::matrix_b, 16, 16, 16, __nv_bfloat16, wmma::col_major> bhi, blo;
                wmma::load_matrix_sync(bhi, &sBhi[n * LDS_K + k16], LDS_K);
                wmma::load_matrix_sync(blo, &sBlo[n * LDS_K + k16], LDS_K);
                #pragma unroll
                for (int mt = 0; mt < 2; mt++) {
                    wmma::mma_sync(acc[mt][nt], ahi[mt], bhi, acc[mt][nt]);
                    wmma::mma_sync(acc[mt][nt], alo[mt], bhi, acc[mt][nt]);
                    wmma::mma_sync(acc[mt][nt], ahi[mt], blo, acc[mt][nt]);
                }
            }
        }
    }

    __syncthreads();
    #pragma unroll
    for (int mt = 0; mt < 2; mt++) {
        int r0 = row0 + wm * 32 + mt * 16;
        #pragma unroll
        for (int nt = 0; nt < 4; nt++) {
            int c0 = wn * 64 + nt * 16;
            if (TO_GH || r0 + 16 <= N_NODES) {
                wmma::store_matrix_sync(&dstp[r0 * OUTF + c0], acc[mt][nt], OUTF, wmma::mem_row_major);
            } else {
                float* st = sF + wid * 256;
                wmma::store_matrix_sync(st, acc[mt][nt], 16, wmma::mem_row_major);
                __syncwarp();
                for (int i = lane; i < 256; i += 32) {
                    int rr = r0 + (i >> 4);
                    if (rr < N_NODES) dstp[rr * OUTF + c0 + (i & 15)] = st[i];
                }
                __syncwarp();
            }
        }
    }
}

// ---------------- launch ----------------
extern "C" void kernel_launch(void* const* d_in, const int* in_sizes, int n_in,
                              void* d_out, int out_size) {
    const float* feat    = (const float*)d_in[0];
    const float* weight  = (const float*)d_in[1];
    const int*   src     = (const int*)d_in[2];
    const int*   dst     = (const int*)d_in[3];
    const float* W_pool  = (const float*)d_in[4];
    const float* b_pool  = (const float*)d_in[5];
    const float* W_neigh = (const float*)d_in[6];
    const float* b_neigh = (const float*)d_in[7];
    float*       out     = (float*)d_out;

    cudaFuncSetAttribute(gemm_wmma_kernel<false, 128, true,  false>,
                         cudaFuncAttributeMaxDynamicSharedMemorySize, SMEM_SZ);
    cudaFuncSetAttribute(gemm_wmma_kernel<false, 256, false, false>,
                         cudaFuncAttributeMaxDynamicSharedMemorySize, SMEM_SZ);
    cudaFuncSetAttribute(gemm_wmma_kernel<true,  256, false, true>,
                         cudaFuncAttributeMaxDynamicSharedMemorySize, SMEM_SZ);

    cudaStream_t aux;
    cudaStreamCreate(&aux);
    cudaEvent_t evFork, evJ1, evJ2;
    cudaEventCreateWithFlags(&evFork, cudaEventDisableTiming);
    cudaEventCreateWithFlags(&evJ1,   cudaEventDisableTiming);
    cudaEventCreateWithFlags(&evJ2,   cudaEventDisableTiming);

    cudaEventRecord(evFork, 0);
    cudaStreamWaitEvent(aux, evFork, 0);

    // main: CSR build chain
    zero_deg_kernel<<<(N_NODES + 255) / 256, 256>>>();
    hist_kernel<<<(N_EDGES + 255) / 256, 256>>>(dst);
    scan_p1<<<NBLK, 1024>>>();
    scan_p3<<<NBLK, 1024>>>();
    scatter_kernel<<<(N_EDGES + 255) / 256, 256>>>(src, dst, weight);

    // aux: gemm1 (-> g_h), then gemm2a (feat half -> out partial)
    gemm_wmma_kernel<false, 128, true, false><<<NTILES, 256, SMEM_SZ, aux>>>(feat, W_pool, b_pool, nullptr);
    cudaEventRecord(evJ1, aux);
    gemm_wmma_kernel<false, 256, false, false><<<NTILES, 256, SMEM_SZ, aux>>>(feat, W_neigh, b_neigh, out);
    cudaEventRecord(evJ2, aux);

    // main: reduce needs scatter (main) + gemm1 (evJ1); writes bf16 planes
    cudaStreamWaitEvent(0, evJ1, 0);
    reduce_kernel<<<(N_NODES + 7) / 8, 256>>>();

    // main: gemm2b (A from planes, accumulate into out) needs reduce + gemm2a (evJ2)
    cudaStreamWaitEvent(0, evJ2, 0);
    gemm_wmma_kernel<true, 256, false, true><<<NTILES, 256, SMEM_SZ>>>(nullptr, W_neigh + D, b_neigh, out);
}

// round 17
// speedup vs baseline: 1.4793x; 1.0140x over previous
#include <cuda_runtime.h>
#include <cuda_bf16.h>
#include <mma.h>
#include <float.h>
#include <stdint.h>

using namespace nvcuda;

#define N_NODES 50000
#define N_PAD   50048
#define N_EDGES 640000
#define D       128
#define OUTF    128
#define TM      128
#define LDS_K   48
#define NBLK    49
#define NTILES  391

// ---------------- device scratch ----------------
__device__ __align__(16) float g_h[N_PAD * D];
__device__ __align__(16) __nv_bfloat16 g_nhi[N_PAD * D];   // neigh hi plane
__device__ __align__(16) __nv_bfloat16 g_nlo[N_PAD * D];   // neigh lo plane
__device__ int   g_deg[N_NODES];
__device__ int   g_start[N_NODES + 1];
__device__ int   g_cursor[N_NODES];
__device__ int   g_part[NBLK];
__device__ __align__(16) int2 g_edge[N_EDGES];   // packed (src, weight-bits)

__device__ __forceinline__ int clampN(int v) { return min(max(v, 0), N_NODES - 1); }

__device__ __forceinline__ void split_bf16(float x, __nv_bfloat16& h, __nv_bfloat16& l) {
    h = __float2bfloat16_rn(x);
    l = __float2bfloat16_rn(x - __bfloat162float(h));
}
__device__ __forceinline__ unsigned pack2(__nv_bfloat16 a, __nv_bfloat16 b) {
    __nv_bfloat162 t(a, b);
    return *(unsigned*)&t;
}

// ---------------- CSR build ----------------
__global__ void zero_deg_kernel() {
    int i = blockIdx.x * blockDim.x + threadIdx.x;
    if (i < N_NODES) g_deg[i] = 0;
}

__global__ void hist_kernel(const int* __restrict__ dst) {
    int e = blockIdx.x * blockDim.x + threadIdx.x;
    if (e < N_EDGES) atomicAdd(&g_deg[clampN(dst[e])], 1);
}

__global__ __launch_bounds__(1024) void scan_p1() {
    int t = threadIdx.x, idx = blockIdx.x * 1024 + t;
    int v = (idx < N_NODES) ? g_deg[idx] : 0;
    #pragma unroll
    for (int off = 16; off > 0; off >>= 1) v += __shfl_down_sync(0xFFFFFFFFu, v, off);
    __shared__ int sh[32];
    if ((t & 31) == 0) sh[t >> 5] = v;
    __syncthreads();
    if (t < 32) {
        int x = sh[t];
        #pragma unroll
        for (int off = 16; off > 0; off >>= 1) x += __shfl_down_sync(0xFFFFFFFFu, x, off);
        if (t == 0) g_part[blockIdx.x] = x;
    }
}

// scan p3: warp-shuffle block scan, block offset from g_part
__global__ __launch_bounds__(1024) void scan_p3() {
    __shared__ int swarp[32];
    __shared__ int s_boff;
    const int b = blockIdx.x, t = threadIdx.x, idx = b * 1024 + t;
    const int lane = t & 31, wrp = t >> 5;

    if (t < 32) {
        int acc = 0;
        for (int j = t; j < b; j += 32) acc += g_part[j];
        #pragma unroll
        for (int off = 16; off > 0; off >>= 1) acc += __shfl_down_sync(0xFFFFFFFFu, acc, off);
        if (t == 0) s_boff = acc;
    }

    int v = (idx < N_NODES) ? g_deg[idx] : 0;
    int incl = v;
    #pragma unroll
    for (int off = 1; off < 32; off <<= 1) {
        int x = __shfl_up_sync(0xFFFFFFFFu, incl, off);
        if (lane >= off) incl += x;
    }
    if (lane == 31) swarp[wrp] = incl;
    __syncthreads();
    if (t < 32) {
        int x = swarp[t];
        int ws = x;
        #pragma unroll
        for (int off = 1; off < 32; off <<= 1) {
            int y = __shfl_up_sync(0xFFFFFFFFu, ws, off);
            if (t >= off) ws += y;
        }
        swarp[t] = ws - x;
    }
    __syncthreads();
    int excl = s_boff + swarp[wrp] + incl - v;
    if (idx < N_NODES) { g_start[idx] = excl; g_cursor[idx] = excl; }
    if (idx == N_NODES - 1) g_start[N_NODES] = excl + v;
}

__global__ void scatter_kernel(const int* __restrict__ src, const int* __restrict__ dst,
                               const float* __restrict__ weight) {
    int e = blockIdx.x * blockDim.x + threadIdx.x;
    if (e >= N_EDGES) return;
    int d = clampN(dst[e]);
    int pos = atomicAdd(&g_cursor[d], 1);
    g_edge[pos] = make_int2(clampN(src[e]), __float_as_int(weight[e]));
}

// ---------------- warp-per-node max reduce, MLP=8, -> bf16 hi/lo planes ----------------
__global__ __launch_bounds__(256) void reduce_kernel() {
    const int node = (blockIdx.x << 3) + (threadIdx.x >> 5);
    const int lane = threadIdx.x & 31;
    if (node >= N_NODES) return;
    const int beg = g_start[node], end = g_start[node + 1];
    const int col = lane * 4;
    float4 acc = make_float4(-FLT_MAX, -FLT_MAX, -FLT_MAX, -FLT_MAX);
    int i = beg;
    for (; i + 8 <= end; i += 8) {                    // 8 rows in flight
        int2 e0 = g_edge[i],   e1 = g_edge[i+1], e2 = g_edge[i+2], e3 = g_edge[i+3];
        int2 e4 = g_edge[i+4], e5 = g_edge[i+5], e6 = g_edge[i+6], e7 = g_edge[i+7];
        float4 v0 = *(const float4*)&g_h[e0.x*D + col];
        float4 v1 = *(const float4*)&g_h[e1.x*D + col];
        float4 v2 = *(const float4*)&g_h[e2.x*D + col];
        float4 v3 = *(const float4*)&g_h[e3.x*D + col];
        float4 v4 = *(const float4*)&g_h[e4.x*D + col];
        float4 v5 = *(const float4*)&g_h[e5.x*D + col];
        float4 v6 = *(const float4*)&g_h[e6.x*D + col];
        float4 v7 = *(const float4*)&g_h[e7.x*D + col];
        float w0 = __int_as_float(e0.y), w1 = __int_as_float(e1.y);
        float w2 = __int_as_float(e2.y), w3 = __int_as_float(e3.y);
        float w4 = __int_as_float(e4.y), w5 = __int_as_float(e5.y);
        float w6 = __int_as_float(e6.y), w7 = __int_as_float(e7.y);
        acc.x = fmaxf(acc.x, v0.x*w0); acc.y = fmaxf(acc.y, v0.y*w0);
        acc.z = fmaxf(acc.z, v0.z*w0); acc.w = fmaxf(acc.w, v0.w*w0);
        acc.x = fmaxf(acc.x, v1.x*w1); acc.y = fmaxf(acc.y, v1.y*w1);
        acc.z = fmaxf(acc.z, v1.z*w1); acc.w = fmaxf(acc.w, v1.w*w1);
        acc.x = fmaxf(acc.x, v2.x*w2); acc.y = fmaxf(acc.y, v2.y*w2);
        acc.z = fmaxf(acc.z, v2.z*w2); acc.w = fmaxf(acc.w, v2.w*w2);
        acc.x = fmaxf(acc.x, v3.x*w3); acc.y = fmaxf(acc.y, v3.y*w3);
        acc.z = fmaxf(acc.z, v3.z*w3); acc.w = fmaxf(acc.w, v3.w*w3);
        acc.x = fmaxf(acc.x, v4.x*w4); acc.y = fmaxf(acc.y, v4.y*w4);
        acc.z = fmaxf(acc.z, v4.z*w4); acc.w = fmaxf(acc.w, v4.w*w4);
        acc.x = fmaxf(acc.x, v5.x*w5); acc.y = fmaxf(acc.y, v5.y*w5);
        acc.z = fmaxf(acc.z, v5.z*w5); acc.w = fmaxf(acc.w, v5.w*w5);
        acc.x = fmaxf(acc.x, v6.x*w6); acc.y = fmaxf(acc.y, v6.y*w6);
        acc.z = fmaxf(acc.z, v6.z*w6); acc.w = fmaxf(acc.w, v6.w*w6);
        acc.x = fmaxf(acc.x, v7.x*w7); acc.y = fmaxf(acc.y, v7.y*w7);
        acc.z = fmaxf(acc.z, v7.z*w7); acc.w = fmaxf(acc.w, v7.w*w7);
    }
    if (i + 4 <= end) {
        int2 e0 = g_edge[i], e1 = g_edge[i+1], e2 = g_edge[i+2], e3 = g_edge[i+3];
        float4 v0 = *(const float4*)&g_h[e0.x*D + col];
        float4 v1 = *(const float4*)&g_h[e1.x*D + col];
        float4 v2 = *(const float4*)&g_h[e2.x*D + col];
        float4 v3 = *(const float4*)&g_h[e3.x*D + col];
        float w0 = __int_as_float(e0.y), w1 = __int_as_float(e1.y);
        float w2 = __int_as_float(e2.y), w3 = __int_as_float(e3.y);
        acc.x = fmaxf(acc.x, v0.x*w0); acc.y = fmaxf(acc.y, v0.y*w0);
        acc.z = fmaxf(acc.z, v0.z*w0); acc.w = fmaxf(acc.w, v0.w*w0);
        acc.x = fmaxf(acc.x, v1.x*w1); acc.y = fmaxf(acc.y, v1.y*w1);
        acc.z = fmaxf(acc.z, v1.z*w1); acc.w = fmaxf(acc.w, v1.w*w1);
        acc.x = fmaxf(acc.x, v2.x*w2); acc.y = fmaxf(acc.y, v2.y*w2);
        acc.z = fmaxf(acc.z, v2.z*w2); acc.w = fmaxf(acc.w, v2.w*w2);
        acc.x = fmaxf(acc.x, v3.x*w3); acc.y = fmaxf(acc.y, v3.y*w3);
        acc.z = fmaxf(acc.z, v3.z*w3); acc.w = fmaxf(acc.w, v3.w*w3);
        i += 4;
    }
    for (; i < end; i++) {
        int2 e = g_edge[i];
        float w = __int_as_float(e.y);
        float4 v = *(const float4*)&g_h[e.x*D + col];
        acc.x = fmaxf(acc.x, v.x*w); acc.y = fmaxf(acc.y, v.y*w);
        acc.z = fmaxf(acc.z, v.z*w); acc.w = fmaxf(acc.w, v.w*w);
    }
    if (beg == end) acc = make_float4(0.f, 0.f, 0.f, 0.f);
    __nv_bfloat16 h0, h1, h2, h3, l0, l1, l2, l3;
    split_bf16(acc.x, h0, l0); split_bf16(acc.y, h1, l1);
    split_bf16(acc.z, h2, l2); split_bf16(acc.w, h3, l3);
    *(uint2*)&g_nhi[node*D + col] = make_uint2(pack2(h0, h1), pack2(h2, h3));
    *(uint2*)&g_nlo[node*D + col] = make_uint2(pack2(l0, l1), pack2(l2, l3));
}

// ---------------- wmma bf16 3-pass GEMM, K=128 ----------------
static constexpr int SM_REG   = 128 * LDS_K;
static constexpr int SM_F_OFF = 4 * SM_REG * 2;
static constexpr int SMEM_SZ  = SM_F_OFF + 16 * 128 * 4;

template<bool A_PLANES, int WSTR, bool TO_GH, bool ACCUM>
__global__ __launch_bounds__(256) void gemm_wmma_kernel(const float* __restrict__ A0,
                                                        const float* __restrict__ W,
                                                        const float* __restrict__ bias,
                                                        float* __restrict__ outp) {
    extern __shared__ char smem[];
    __nv_bfloat16* sAhi = (__nv_bfloat16*)smem;
    __nv_bfloat16* sAlo = sAhi + SM_REG;
    __nv_bfloat16* sBhi = sAlo + SM_REG;
    __nv_bfloat16* sBlo = sBhi + SM_REG;
    float*         sF   = (float*)(smem + SM_F_OFF);

    const int tid  = threadIdx.x;
    const int lane = tid & 31;
    const int wid  = tid >> 5;
    const int wm   = wid >> 1;
    const int wn   = wid & 1;
    const int row0 = blockIdx.x * TM;

    float* dstp = TO_GH ? g_h : outp;                 // device symbol ref (shadow-ptr trap!)

    wmma::fragment<wmma::accumulator, 16, 16, 16, float> acc[2][4];
    if (!ACCUM) {
        for (int i = tid; i < 16 * 128; i += 256) sF[i] = bias[i & 127];
        __syncthreads();
        #pragma unroll
        for (int mt = 0; mt < 2; mt++)
            #pragma unroll
            for (int nt = 0; nt < 4; nt++)
                wmma::load_matrix_sync(acc[mt][nt], sF + wn * 64 + nt * 16, 128, wmma::mem_row_major);
        __syncthreads();
    } else {
        #pragma unroll
        for (int mt = 0; mt < 2; mt++) {
            int r0 = row0 + wm * 32 + mt * 16;
            #pragma unroll
            for (int nt = 0; nt < 4; nt++) {
                int c0 = wn * 64 + nt * 16;
                if (r0 + 16 <= N_NODES) {
                    wmma::load_matrix_sync(acc[mt][nt], &outp[r0 * OUTF + c0], OUTF, wmma::mem_row_major);
                } else {
                    float* st = sF + wid * 256;
                    for (int i = lane; i < 256; i += 32) {
                        int rr = min(r0 + (i >> 4), N_NODES - 1);
                        st[i] = outp[rr * OUTF + c0 + (i & 15)];
                    }
                    __syncwarp();
                    wmma::load_matrix_sync(acc[mt][nt], st, 16, wmma::mem_row_major);
                    __syncwarp();
                }
            }
        }
        __syncthreads();
    }

    for (int c = 0; c < 4; c++) {
        const int k0 = c * 32;
        if (c > 0) __syncthreads();

        #pragma unroll
        for (int t = 0; t < 4; t++) {                 // A chunk
            int g = tid + t * 256;
            int row = g >> 3, kc = (g & 7) * 4;
            int grow = row0 + row;
            int o = row * LDS_K + kc;
            if (A_PLANES) {
                uint2 vh = (grow < N_NODES) ? *(const uint2*)&g_nhi[grow * D + k0 + kc]
                                            : make_uint2(0, 0);
                uint2 vl = (grow < N_NODES) ? *(const uint2*)&g_nlo[grow * D + k0 + kc]
                                            : make_uint2(0, 0);
                *(uint2*)&sAhi[o] = vh;
                *(uint2*)&sAlo[o] = vl;
            } else {
                float4 v = (grow < N_NODES) ? *(const float4*)&A0[grow * D + k0 + kc]
                                            : make_float4(0.f, 0.f, 0.f, 0.f);
                __nv_bfloat16 h0, h1, h2, h3, l0, l1, l2, l3;
                split_bf16(v.x, h0, l0); split_bf16(v.y, h1, l1);
                split_bf16(v.z, h2, l2); split_bf16(v.w, h3, l3);
                *(uint2*)&sAhi[o] = make_uint2(pack2(h0, h1), pack2(h2, h3));
                *(uint2*)&sAlo[o] = make_uint2(pack2(l0, l1), pack2(l2, l3));
            }
        }
        #pragma unroll
        for (int t = 0; t < 4; t++) {                 // B chunk: W[n][k], stride WSTR
            int g = tid + t * 256;
            int row = g >> 3, kc = (g & 7) * 4;
            float4 v = *(const float4*)&W[row * WSTR + k0 + kc];
            __nv_bfloat16 h0, h1, h2, h3, l0, l1, l2, l3;
            split_bf16(v.x, h0, l0); split_bf16(v.y, h1, l1);
            split_bf16(v.z, h2, l2); split_bf16(v.w, h3, l3);
            int o = row * LDS_K + kc;
            *(uint2*)&sBhi[o] = make_uint2(pack2(h0, h1), pack2(h2, h3));
            *(uint2*)&sBlo[o] = make_uint2(pack2(l0, l1), pack2(l2, l3));
        }
        __syncthreads();

        #pragma unroll
        for (int ks = 0; ks < 2; ks++) {
            const int k16 = ks * 16;
            wmma::fragment<wmma::matrix_a, 16, 16, 16, __nv_bfloat16, wmma::row_major> ahi[2], alo[2];
            #pragma unroll
            for (int mt = 0; mt < 2; mt++) {
                int r = wm * 32 + mt * 16;
                wmma::load_matrix_sync(ahi[mt], &sAhi[r * LDS_K + k16], LDS_K);
                wmma::load_matrix_sync(alo[mt], &sAlo[r * LDS_K + k16], LDS_K);
            }
            #pragma unroll
            for (int nt = 0; nt < 4; nt++) {
                int n = wn * 64 + nt * 16;
                wmma::fragment<wmma::matrix_b, 16, 16, 16, __nv_bfloat16, wmma::col_major> bhi, blo;
                wmma::load_matrix_sync(bhi, &sBhi[n * LDS_K + k16], LDS_K);
                wmma::load_matrix_sync(blo, &sBlo[n * LDS_K + k16], LDS_K);
                #pragma unroll
                for (int mt = 0; mt < 2; mt++) {
                    wmma::mma_sync(acc[mt][nt], ahi[mt], bhi, acc[mt][nt]);
                    wmma::mma_sync(acc[mt][nt], alo[mt], bhi, acc[mt][nt]);
                    wmma::mma_sync(acc[mt][nt], ahi[mt], blo, acc[mt][nt]);
                }
            }
        }
    }

    __syncthreads();
    #pragma unroll
    for (int mt = 0; mt < 2; mt++) {
        int r0 = row0 + wm * 32 + mt * 16;
        #pragma unroll
        for (int nt = 0; nt < 4; nt++) {
            int c0 = wn * 64 + nt * 16;
            if (TO_GH || r0 + 16 <= N_NODES) {
                wmma::store_matrix_sync(&dstp[r0 * OUTF + c0], acc[mt][nt], OUTF, wmma::mem_row_major);
            } else {
                float* st = sF + wid * 256;
                wmma::store_matrix_sync(st, acc[mt][nt], 16, wmma::mem_row_major);
                __syncwarp();
                for (int i = lane; i < 256; i += 32) {
                    int rr = r0 + (i >> 4);
                    if (rr < N_NODES) dstp[rr * OUTF + c0 + (i & 15)] = st[i];
                }
                __syncwarp();
            }
        }
    }
}

// ---------------- launch ----------------
extern "C" void kernel_launch(void* const* d_in, const int* in_sizes, int n_in,
                              void* d_out, int out_size) {
    const float* feat    = (const float*)d_in[0];
    const float* weight  = (const float*)d_in[1];
    const int*   src     = (const int*)d_in[2];
    const int*   dst     = (const int*)d_in[3];
    const float* W_pool  = (const float*)d_in[4];
    const float* b_pool  = (const float*)d_in[5];
    const float* W_neigh = (const float*)d_in[6];
    const float* b_neigh = (const float*)d_in[7];
    float*       out     = (float*)d_out;

    cudaFuncSetAttribute(gemm_wmma_kernel<false, 128, true,  false>,
                         cudaFuncAttributeMaxDynamicSharedMemorySize, SMEM_SZ);
    cudaFuncSetAttribute(gemm_wmma_kernel<false, 256, false, false>,
                         cudaFuncAttributeMaxDynamicSharedMemorySize, SMEM_SZ);
    cudaFuncSetAttribute(gemm_wmma_kernel<true,  256, false, true>,
                         cudaFuncAttributeMaxDynamicSharedMemorySize, SMEM_SZ);

    cudaStream_t aux;
    cudaStreamCreate(&aux);
    cudaEvent_t evFork, evJ1, evJ2;
    cudaEventCreateWithFlags(&evFork, cudaEventDisableTiming);
    cudaEventCreateWithFlags(&evJ1,   cudaEventDisableTiming);
    cudaEventCreateWithFlags(&evJ2,   cudaEventDisableTiming);

    cudaEventRecord(evFork, 0);
    cudaStreamWaitEvent(aux, evFork, 0);

    // main: CSR build chain
    zero_deg_kernel<<<(N_NODES + 255) / 256, 256>>>();
    hist_kernel<<<(N_EDGES + 255) / 256, 256>>>(dst);
    scan_p1<<<NBLK, 1024>>>();
    scan_p3<<<NBLK, 1024>>>();
    scatter_kernel<<<(N_EDGES + 255) / 256, 256>>>(src, dst, weight);

    // aux: gemm1 (-> g_h), then gemm2a (feat half -> out partial)
    gemm_wmma_kernel<false, 128, true, false><<<NTILES, 256, SMEM_SZ, aux>>>(feat, W_pool, b_pool, nullptr);
    cudaEventRecord(evJ1, aux);
    gemm_wmma_kernel<false, 256, false, false><<<NTILES, 256, SMEM_SZ, aux>>>(feat, W_neigh, b_neigh, out);
    cudaEventRecord(evJ2, aux);

    // main: reduce needs scatter (main) + gemm1 (evJ1); writes bf16 planes
    cudaStreamWaitEvent(0, evJ1, 0);
    reduce_kernel<<<(N_NODES + 7) / 8, 256>>>();

    // main: gemm2b (A from planes, accumulate into out) needs reduce + gemm2a (evJ2)
    cudaStreamWaitEvent(0, evJ2, 0);
    gemm_wmma_kernel<true, 256, false, true><<<NTILES, 256, SMEM_SZ>>>(nullptr, W_neigh + D, b_neigh, out);
}